// round 4
// baseline (speedup 1.0000x reference)
#include <cuda_runtime.h>
#include <math.h>
#include <stdint.h>

#define B_ 32768
#define M_ 10
#define BM_ (B_*M_)

// Scratch
__device__ float g_curx[(size_t)B_ * 1024];   // [z_top | r_top | h_top | q] per batch
__device__ float g_k  [(size_t)BM_ * 256];

__device__ __forceinline__ float sigmoidf_(float x) { return 1.f / (1.f + expf(-x)); }

__device__ __forceinline__ uint32_t smem_u32(const void* p) {
    return (uint32_t)__cvta_generic_to_shared(p);
}
__device__ __forceinline__ void cp_async16(uint32_t s, const void* g) {
    asm volatile("cp.async.cg.shared.global [%0], [%1], 16;\n" :: "r"(s), "l"(g));
}
__device__ __forceinline__ void cp_commit() {
    asm volatile("cp.async.commit_group;\n");
}
template<int N>
__device__ __forceinline__ void cp_wait() {
    asm volatile("cp.async.wait_group %0;\n" :: "n"(N));
}

__device__ __forceinline__ void mma_tf32(float c[4], const uint32_t a[4], const uint32_t b[2]) {
    asm volatile(
        "mma.sync.aligned.m16n8k8.row.col.f32.tf32.tf32.f32 "
        "{%0,%1,%2,%3}, {%4,%5,%6,%7}, {%8,%9}, {%0,%1,%2,%3};"
        : "+f"(c[0]), "+f"(c[1]), "+f"(c[2]), "+f"(c[3])
        : "r"(a[0]), "r"(a[1]), "r"(a[2]), "r"(a[3]), "r"(b[0]), "r"(b[1]));
}

// ===========================================================================
// Kernel 1: curx = cur @ [Wz_top|Wr_top|Wh_top|Wq] + bias  (round-3 MODE 0)
// 128x128 tile, tf32 HMMA, cp.async double-buffered.
// ===========================================================================
#define AS_STRIDE 36
#define BS_STRIDE 136
#define AS_ELEMS (128 * AS_STRIDE)
#define BS_ELEMS (32 * BS_STRIDE)

__global__ __launch_bounds__(256, 2)
void curx_gemm(const float* __restrict__ A,
               const float* __restrict__ Wa, const float* __restrict__ Wb,
               const float* __restrict__ Wc, const float* __restrict__ Wd,
               const float* __restrict__ ba, const float* __restrict__ bb,
               const float* __restrict__ bc, const float* __restrict__ bd)
{
    __shared__ __align__(16) float As[2][AS_ELEMS];
    __shared__ __align__(16) float Bs[2][BS_ELEMS];

    const int tid  = threadIdx.x;
    const int lane = tid & 31;
    const int warp = tid >> 5;
    const int wm   = warp >> 2;
    const int wn   = warp & 3;
    const int q    = lane >> 2;
    const int t4   = lane & 3;

    const int n0  = blockIdx.x * 128;
    const int m0  = blockIdx.y * 128;
    const int seg = n0 >> 8;
    const int ncol = n0 & 255;

    const float* W    = (seg == 0) ? Wa : (seg == 1) ? Wb : (seg == 2) ? Wc : Wd;
    const float* bias = (seg == 0) ? ba : (seg == 1) ? bb : (seg == 2) ? bc : bd;

    float acc[4][4][4];
    #pragma unroll
    for (int i = 0; i < 4; i++)
        #pragma unroll
        for (int j = 0; j < 4; j++)
            #pragma unroll
            for (int v = 0; v < 4; v++) acc[i][j][v] = 0.f;

    auto load_chunk = [&](int bi, int k0) {
        #pragma unroll
        for (int i = 0; i < 4; i++) {
            int g = i * 256 + tid;
            int m = g >> 3, c4 = (g & 7) << 2;
            cp_async16(smem_u32(&As[bi][m * AS_STRIDE + c4]),
                       A + (size_t)(m0 + m) * 256 + k0 + c4);
        }
        #pragma unroll
        for (int i = 0; i < 4; i++) {
            int g = i * 256 + tid;
            int k = g >> 5, n4 = (g & 31) << 2;
            cp_async16(smem_u32(&Bs[bi][k * BS_STRIDE + n4]),
                       W + (size_t)(k0 + k) * 256 + ncol + n4);
        }
        cp_commit();
    };

    load_chunk(0, 0);

    for (int c = 0; c < 8; c++) {
        const int buf = c & 1;
        if (c < 7) load_chunk(buf ^ 1, (c + 1) * 32);
        if (c < 7) cp_wait<1>(); else cp_wait<0>();
        __syncthreads();

        const float* Asb = As[buf];
        const float* Bsb = Bs[buf];
        #pragma unroll
        for (int kk = 0; kk < 4; kk++) {
            uint32_t a[4][4], b[4][2];
            const int col = kk * 8 + t4;
            #pragma unroll
            for (int mt = 0; mt < 4; mt++) {
                const int r0 = wm * 64 + mt * 16 + q;
                a[mt][0] = __float_as_uint(Asb[r0 * AS_STRIDE + col]);
                a[mt][1] = __float_as_uint(Asb[(r0 + 8) * AS_STRIDE + col]);
                a[mt][2] = __float_as_uint(Asb[r0 * AS_STRIDE + col + 4]);
                a[mt][3] = __float_as_uint(Asb[(r0 + 8) * AS_STRIDE + col + 4]);
            }
            #pragma unroll
            for (int nt = 0; nt < 4; nt++) {
                const int nb = wn * 32 + nt * 8 + q;
                b[nt][0] = __float_as_uint(Bsb[col * BS_STRIDE + nb]);
                b[nt][1] = __float_as_uint(Bsb[(col + 4) * BS_STRIDE + nb]);
            }
            #pragma unroll
            for (int mt = 0; mt < 4; mt++)
                #pragma unroll
                for (int nt = 0; nt < 4; nt++)
                    mma_tf32(acc[mt][nt], a[mt], b[nt]);
        }
        __syncthreads();
    }

    #pragma unroll
    for (int mt = 0; mt < 4; mt++) {
        #pragma unroll
        for (int nt = 0; nt < 4; nt++) {
            const int hl = wn * 32 + nt * 8 + 2 * t4;
            const int h  = ncol + hl;
            #pragma unroll
            for (int half = 0; half < 2; half++) {
                const int row = m0 + wm * 64 + mt * 16 + q + half * 8;
                float2 bb2 = *(const float2*)(bias + h);
                float2 o = make_float2(acc[mt][nt][half * 2 + 0] + bb2.x,
                                       acc[mt][nt][half * 2 + 1] + bb2.y);
                *(float2*)(g_curx + (size_t)row * 1024 + seg * 256 + h) = o;
            }
        }
    }
}

// ===========================================================================
// Kernel 2: fused GRU + k-projection. One CTA = 64 rows of BM, all 256 cols.
//   GEMM-Z: z = sigmoid(prev@Wzb + curx_z)          (z kept in registers)
//   GEMM-R: rp = sigmoid(prev@Wrb + curx_r) * prev  -> smem
//   GEMM-H: cand = tanh(rp@Whb + curx_h); upd = (1-z)p + z*cand -> gmem + smem
//   GEMM-K: k = upd@Wk + bk -> g_k
// ===========================================================================
#define RT  64
#define FAST 36       // As stride (4 mod 32: conflict-free frags)
#define FBST 264      // Bs stride (8 mod 32: conflict-free frags)
#define FSST 260      // Ssm stride (4 mod 32)
#define FUSED_SMEM ((RT*FSST + 2*RT*FAST + 2*32*FBST) * sizeof(float))

__global__ __launch_bounds__(256, 1)
void fused_gru(const float* __restrict__ prev,
               const float* __restrict__ Wzb, const float* __restrict__ Wrb,
               const float* __restrict__ Whb, const float* __restrict__ Wk,
               const float* __restrict__ bk,
               float* __restrict__ upd_out)
{
    extern __shared__ float dsm[];
    float* Ssm = dsm;                       // RT*FSST  (rp, then upd)
    float* Asb = dsm + RT * FSST;           // 2 * RT*FAST
    float* Bsb = Asb + 2 * RT * FAST;       // 2 * 32*FBST

    const int tid  = threadIdx.x;
    const int lane = tid & 31;
    const int warp = tid >> 5;
    const int wm   = warp >> 2;       // 0..1 : 32 rows each
    const int wn   = warp & 3;        // 0..3 : 64 cols each
    const int q    = lane >> 2;
    const int t4   = lane & 3;
    const int m0   = blockIdx.x * RT;

    float acc[2][8][4];
    float zreg[2][8][4];

    auto loadB = [&](int buf, int k0, const float* W) {
        #pragma unroll
        for (int i = 0; i < 8; i++) {
            int g = i * 256 + tid;
            int k = g >> 6, n4 = (g & 63) << 2;
            cp_async16(smem_u32(&Bsb[buf * 32 * FBST + k * FBST + n4]),
                       W + (size_t)(k0 + k) * 256 + n4);
        }
    };
    auto loadA = [&](int buf, int k0) {
        #pragma unroll
        for (int i = 0; i < 2; i++) {
            int g = i * 256 + tid;
            int m = g >> 3, c4 = (g & 7) << 2;
            cp_async16(smem_u32(&Asb[buf * RT * FAST + m * FAST + c4]),
                       prev + (size_t)(m0 + m) * 256 + k0 + c4);
        }
    };

    auto run_gemm = [&](const float* W, bool streamA) {
        #pragma unroll
        for (int i = 0; i < 2; i++)
            #pragma unroll
            for (int j = 0; j < 8; j++)
                #pragma unroll
                for (int v = 0; v < 4; v++) acc[i][j][v] = 0.f;

        if (streamA) loadA(0, 0);
        loadB(0, 0, W);
        cp_commit();

        for (int c = 0; c < 8; c++) {
            const int buf = c & 1;
            if (c < 7) {
                if (streamA) loadA(buf ^ 1, (c + 1) * 32);
                loadB(buf ^ 1, (c + 1) * 32, W);
                cp_commit();
                cp_wait<1>();
            } else {
                cp_wait<0>();
            }
            __syncthreads();

            const float* Ab  = streamA ? &Asb[buf * RT * FAST] : Ssm;
            const int    ast = streamA ? FAST : FSST;
            const int    cb  = streamA ? 0 : c * 32;
            const float* Bb  = &Bsb[buf * 32 * FBST];

            #pragma unroll
            for (int kk = 0; kk < 4; kk++) {
                const int col = cb + kk * 8 + t4;
                uint32_t a[2][4], b[8][2];
                #pragma unroll
                for (int mt = 0; mt < 2; mt++) {
                    const int r0 = wm * 32 + mt * 16 + q;
                    a[mt][0] = __float_as_uint(Ab[r0 * ast + col]);
                    a[mt][1] = __float_as_uint(Ab[(r0 + 8) * ast + col]);
                    a[mt][2] = __float_as_uint(Ab[r0 * ast + col + 4]);
                    a[mt][3] = __float_as_uint(Ab[(r0 + 8) * ast + col + 4]);
                }
                #pragma unroll
                for (int nt = 0; nt < 8; nt++) {
                    const int nb = wn * 64 + nt * 8 + q;
                    b[nt][0] = __float_as_uint(Bb[(kk * 8 + t4) * FBST + nb]);
                    b[nt][1] = __float_as_uint(Bb[(kk * 8 + t4 + 4) * FBST + nb]);
                }
                #pragma unroll
                for (int mt = 0; mt < 2; mt++)
                    #pragma unroll
                    for (int nt = 0; nt < 8; nt++)
                        mma_tf32(acc[mt][nt], a[mt], b[nt]);
            }
            __syncthreads();
        }
    };

    // ---- GEMM-Z: z -> registers ----
    run_gemm(Wzb, true);
    #pragma unroll
    for (int mt = 0; mt < 2; mt++) {
        #pragma unroll
        for (int half = 0; half < 2; half++) {
            const int rl = wm * 32 + mt * 16 + q + half * 8;
            const float* cx = g_curx + (size_t)((m0 + rl) / 10) * 1024;
            #pragma unroll
            for (int nt = 0; nt < 8; nt++) {
                const int h = wn * 64 + nt * 8 + 2 * t4;
                float2 c2 = *(const float2*)(cx + h);
                zreg[mt][nt][half * 2 + 0] = sigmoidf_(acc[mt][nt][half * 2 + 0] + c2.x);
                zreg[mt][nt][half * 2 + 1] = sigmoidf_(acc[mt][nt][half * 2 + 1] + c2.y);
            }
        }
    }

    // ---- GEMM-R: rp = sigmoid(.)*prev -> Ssm ----
    run_gemm(Wrb, true);
    #pragma unroll
    for (int mt = 0; mt < 2; mt++) {
        #pragma unroll
        for (int half = 0; half < 2; half++) {
            const int rl  = wm * 32 + mt * 16 + q + half * 8;
            const int row = m0 + rl;
            const float* cx = g_curx + (size_t)(row / 10) * 1024 + 256;
            #pragma unroll
            for (int nt = 0; nt < 8; nt++) {
                const int h = wn * 64 + nt * 8 + 2 * t4;
                float2 c2 = *(const float2*)(cx + h);
                float2 pv = *(const float2*)(prev + (size_t)row * 256 + h);
                float r0 = sigmoidf_(acc[mt][nt][half * 2 + 0] + c2.x) * pv.x;
                float r1 = sigmoidf_(acc[mt][nt][half * 2 + 1] + c2.y) * pv.y;
                *(float2*)(Ssm + rl * FSST + h) = make_float2(r0, r1);
            }
        }
    }
    __syncthreads();

    // ---- GEMM-H: cand + GRU update -> upd_out + Ssm ----
    run_gemm(Whb, false);
    #pragma unroll
    for (int mt = 0; mt < 2; mt++) {
        #pragma unroll
        for (int half = 0; half < 2; half++) {
            const int rl  = wm * 32 + mt * 16 + q + half * 8;
            const int row = m0 + rl;
            const float* cx = g_curx + (size_t)(row / 10) * 1024 + 512;
            #pragma unroll
            for (int nt = 0; nt < 8; nt++) {
                const int h = wn * 64 + nt * 8 + 2 * t4;
                float2 c2 = *(const float2*)(cx + h);
                float2 pv = *(const float2*)(prev + (size_t)row * 256 + h);
                float z0 = zreg[mt][nt][half * 2 + 0];
                float z1 = zreg[mt][nt][half * 2 + 1];
                float c0 = tanhf(acc[mt][nt][half * 2 + 0] + c2.x);
                float c1 = tanhf(acc[mt][nt][half * 2 + 1] + c2.y);
                float u0 = (1.f - z0) * pv.x + z0 * c0;
                float u1 = (1.f - z1) * pv.y + z1 * c1;
                *(float2*)(upd_out + (size_t)row * 256 + h) = make_float2(u0, u1);
                *(float2*)(Ssm + rl * FSST + h) = make_float2(u0, u1);
            }
        }
    }
    __syncthreads();

    // ---- GEMM-K: k = upd @ Wk + bk -> g_k ----
    run_gemm(Wk, false);
    #pragma unroll
    for (int mt = 0; mt < 2; mt++) {
        #pragma unroll
        for (int half = 0; half < 2; half++) {
            const int rl  = wm * 32 + mt * 16 + q + half * 8;
            const int row = m0 + rl;
            #pragma unroll
            for (int nt = 0; nt < 8; nt++) {
                const int h = wn * 64 + nt * 8 + 2 * t4;
                float2 b2 = *(const float2*)(bk + h);
                *(float2*)(g_k + (size_t)row * 256 + h) =
                    make_float2(acc[mt][nt][half * 2 + 0] + b2.x,
                                acc[mt][nt][half * 2 + 1] + b2.y);
            }
        }
    }
}

// ===========================================================================
// Kernel 3: attention + weighted memory + output proj + LayerNorm. GB=32.
// ===========================================================================
#define GB_ 32
#define ATTN_SMEM ((GB_*512 + GB_*80 + GB_*10) * sizeof(float))

__global__ __launch_bounds__(256)
void attn_fuse_kernel(const float* __restrict__ cur,
                      float* __restrict__ d_out,
                      const float* __restrict__ Wo, const float* __restrict__ bo,
                      const float* __restrict__ gamma, const float* __restrict__ beta)
{
    extern __shared__ float dsm[];
    float* sbuf  = dsm;                 // GB*512
    float* ss    = dsm + GB_ * 512;     // GB*80
    float* sattn = ss + GB_ * 80;       // GB*10

    const int tid = threadIdx.x;
    const int b0 = blockIdx.x * GB_;
    float* upd      = d_out + (size_t)B_ * 256;
    float* attn_out = d_out + (size_t)B_ * 256 + (size_t)BM_ * 256;

    // A: load q
    for (int idx = tid; idx < GB_ * 256; idx += 256) {
        int bi = idx >> 8, h = idx & 255;
        sbuf[bi * 512 + h] = g_curx[(size_t)(b0 + bi) * 1024 + 768 + h];
    }
    __syncthreads();

    // B: scores
    const float scale = 0.17677669529663687f;
    for (int t = tid; t < GB_ * 80; t += 256) {
        int bi = t / 80, rem = t % 80, n = rem / 10, m = rem % 10;
        const float* kp = g_k + ((size_t)((b0 + bi) * 10 + m)) * 256 + n * 32;
        const float* qp = sbuf + bi * 512 + n * 32;
        float s = 0.f;
        #pragma unroll
        for (int d4 = 0; d4 < 32; d4 += 4) {
            float4 kv = *(const float4*)(kp + d4);
            float4 qv = *(const float4*)(qp + d4);
            s += kv.x * qv.x + kv.y * qv.y + kv.z * qv.z + kv.w * qv.w;
        }
        ss[t] = s * scale;
    }
    __syncthreads();

    // C: softmax over m
    for (int t = tid; t < GB_ * 8; t += 256) {
        float* row = ss + t * 10;
        float mx = row[0];
        #pragma unroll
        for (int m = 1; m < 10; m++) mx = fmaxf(mx, row[m]);
        float e[10], sum = 0.f;
        #pragma unroll
        for (int m = 0; m < 10; m++) { e[m] = expf(row[m] - mx); sum += e[m]; }
        float inv = 1.f / sum;
        #pragma unroll
        for (int m = 0; m < 10; m++) row[m] = e[m] * inv;
    }
    __syncthreads();

    // head mean
    for (int t = tid; t < GB_ * 10; t += 256) {
        int bi = t / 10, m = t % 10;
        float s = 0.f;
        #pragma unroll
        for (int n = 0; n < 8; n++) s += ss[(bi * 8 + n) * 10 + m];
        s *= 0.125f;
        sattn[t] = s;
        attn_out[(size_t)(b0 + bi) * 10 + m] = s;
    }
    __syncthreads();

    // D: weighted memory; x = [cur | weighted]
    for (int idx = tid; idx < GB_ * 256; idx += 256) {
        int bi = idx >> 8, h = idx & 255;
        size_t base = ((size_t)(b0 + bi) * 10) * 256 + h;
        float s = 0.f;
        #pragma unroll
        for (int m = 0; m < 10; m++) s += upd[base + m * 256] * sattn[bi * 10 + m];
        sbuf[bi * 512 + h]       = cur[(size_t)(b0 + bi) * 256 + h];
        sbuf[bi * 512 + 256 + h] = s;
    }
    __syncthreads();

    // E: fused_pre = x @ Wo + bo
    float accv[GB_];
    #pragma unroll
    for (int bi = 0; bi < GB_; bi++) accv[bi] = bo[tid];
    for (int c = 0; c < 512; c += 4) {
        float w0 = Wo[(size_t)(c + 0) * 256 + tid];
        float w1 = Wo[(size_t)(c + 1) * 256 + tid];
        float w2 = Wo[(size_t)(c + 2) * 256 + tid];
        float w3 = Wo[(size_t)(c + 3) * 256 + tid];
        #pragma unroll
        for (int bi = 0; bi < GB_; bi++) {
            float4 xv = *(const float4*)(sbuf + bi * 512 + c);
            accv[bi] += xv.x * w0 + xv.y * w1 + xv.z * w2 + xv.w * w3;
        }
    }
    __syncthreads();
    #pragma unroll
    for (int bi = 0; bi < GB_; bi++) sbuf[bi * 256 + tid] = accv[bi];
    __syncthreads();

    // F: LayerNorm
    int wid = tid >> 5, lane = tid & 31;
    for (int bi = wid; bi < GB_; bi += 8) {
        float v[8], sum = 0.f;
        #pragma unroll
        for (int i = 0; i < 8; i++) { v[i] = sbuf[bi * 256 + lane + 32 * i]; sum += v[i]; }
        #pragma unroll
        for (int o = 16; o > 0; o >>= 1) sum += __shfl_xor_sync(0xffffffffu, sum, o);
        float mu = sum * (1.f / 256.f);
        float sq = 0.f;
        #pragma unroll
        for (int i = 0; i < 8; i++) { float d = v[i] - mu; sq += d * d; }
        #pragma unroll
        for (int o = 16; o > 0; o >>= 1) sq += __shfl_xor_sync(0xffffffffu, sq, o);
        float rstd = rsqrtf(sq * (1.f / 256.f) + 1e-5f);
        size_t ob = (size_t)(b0 + bi) * 256;
        #pragma unroll
        for (int i = 0; i < 8; i++) {
            int d_ = lane + 32 * i;
            d_out[ob + d_] = (v[i] - mu) * rstd * gamma[d_] + beta[d_];
        }
    }
}

extern "C" void kernel_launch(void* const* d_in, const int* in_sizes, int n_in,
                              void* d_out, int out_size)
{
    (void)in_sizes; (void)n_in; (void)out_size;
    const float* cur    = (const float*)d_in[0];
    const float* prev   = (const float*)d_in[1];
    const float* Wz     = (const float*)d_in[2];
    const float* bz     = (const float*)d_in[3];
    const float* Wr     = (const float*)d_in[4];
    const float* br     = (const float*)d_in[5];
    const float* Wh     = (const float*)d_in[6];
    const float* bh     = (const float*)d_in[7];
    const float* Wq     = (const float*)d_in[8];
    const float* bq     = (const float*)d_in[9];
    const float* Wk     = (const float*)d_in[10];
    const float* bk     = (const float*)d_in[11];
    const float* Wo     = (const float*)d_in[12];
    const float* bo     = (const float*)d_in[13];
    const float* gamma2 = (const float*)d_in[14];
    const float* beta2  = (const float*)d_in[15];
    float* out = (float*)d_out;
    float* upd = out + (size_t)B_ * 256;

    cudaFuncSetAttribute(fused_gru, cudaFuncAttributeMaxDynamicSharedMemorySize,
                         (int)FUSED_SMEM);
    cudaFuncSetAttribute(attn_fuse_kernel, cudaFuncAttributeMaxDynamicSharedMemorySize,
                         (int)ATTN_SMEM);

    dim3 blk(256);
    // 1) cur projections: [B,256] @ [256,1024]
    curx_gemm<<<dim3(8, B_ / 128), blk>>>(cur, Wz, Wr, Wh, Wq, bz, br, bh, bq);
    // 2) fused GRU (z, r, cand, update) + k projection
    fused_gru<<<dim3(BM_ / RT), blk, FUSED_SMEM>>>(prev, Wz + 65536, Wr + 65536,
                                                   Wh + 65536, Wk, bk, upd);
    // 3) attention + weighted memory + output proj + layernorm
    attn_fuse_kernel<<<dim3(B_ / GB_), blk, ATTN_SMEM>>>(cur, out, Wo, bo, gamma2, beta2);
}

// round 5
// speedup vs baseline: 1.4098x; 1.4098x over previous
#include <cuda_runtime.h>
#include <math.h>
#include <stdint.h>

#define B_ 32768
#define M_ 10
#define BM_ (B_*M_)

// Scratch (allocation-free rule: __device__ globals)
__device__ float g_curx[(size_t)B_ * 1024];   // [z_top | r_top | h_top | q] per batch
__device__ float g_z  [(size_t)BM_ * 256];
__device__ float g_rp [(size_t)BM_ * 256];
__device__ float g_k  [(size_t)BM_ * 256];
__device__ float g_x  [(size_t)B_ * 512];     // [cur | weighted_memory]
__device__ float g_f  [(size_t)B_ * 256];     // pre-LayerNorm fused

__device__ __forceinline__ float sigmoidf_(float x) { return 1.f / (1.f + expf(-x)); }

__device__ __forceinline__ uint32_t smem_u32(const void* p) {
    return (uint32_t)__cvta_generic_to_shared(p);
}
__device__ __forceinline__ void cp_async16(uint32_t s, const void* g) {
    asm volatile("cp.async.cg.shared.global [%0], [%1], 16;\n" :: "r"(s), "l"(g));
}
__device__ __forceinline__ void cp_commit() {
    asm volatile("cp.async.commit_group;\n");
}
template<int N>
__device__ __forceinline__ void cp_wait() {
    asm volatile("cp.async.wait_group %0;\n" :: "n"(N));
}

__device__ __forceinline__ void mma_tf32(float c[4], const uint32_t a[4], const uint32_t b[2]) {
    asm volatile(
        "mma.sync.aligned.m16n8k8.row.col.f32.tf32.tf32.f32 "
        "{%0,%1,%2,%3}, {%4,%5,%6,%7}, {%8,%9}, {%0,%1,%2,%3};"
        : "+f"(c[0]), "+f"(c[1]), "+f"(c[2]), "+f"(c[3])
        : "r"(a[0]), "r"(a[1]), "r"(a[2]), "r"(a[3]), "r"(b[0]), "r"(b[1]));
}

// ---------------------------------------------------------------------------
// tf32 tensor-core GEMM, 128x128 tile, cp.async double-buffered.
// MODE 0: curx = cur @ {Wz,Wr,Wh,Wq}(top rows) + bias      -> g_curx   (K=256)
// MODE 1: {z,r} = sigmoid(prev @ {Wz,Wr}(bottom) + curx)   -> g_z, g_rp (K=256)
// MODE 2: cand  = tanh(g_rp @ Wh(bottom) + curx_h); GRU    -> out      (K=256)
// MODE 3: k     = u @ Wk + bk                              -> g_k      (K=256)
// MODE 4: f     = g_x @ Wo + bo                            -> g_f      (K=512)
// ---------------------------------------------------------------------------
#define AS_STRIDE 36
#define BS_STRIDE 136
#define AS_ELEMS (128 * AS_STRIDE)
#define BS_ELEMS (32 * BS_STRIDE)

template<int MODE>
__global__ __launch_bounds__(256, 2)
void mma_gemm(const float* __restrict__ A,
              const float* __restrict__ Wa, const float* __restrict__ Wb,
              const float* __restrict__ Wc, const float* __restrict__ Wd,
              const float* __restrict__ ba, const float* __restrict__ bb,
              const float* __restrict__ bc, const float* __restrict__ bd,
              const float* __restrict__ prev,
              float* __restrict__ out)
{
    __shared__ __align__(16) float As[2][AS_ELEMS];
    __shared__ __align__(16) float Bs[2][BS_ELEMS];

    constexpr int KCH = (MODE == 4) ? 16 : 8;     // 32-wide K chunks
    constexpr int LDA = (MODE == 4) ? 512 : 256;  // A leading dim
    constexpr int LDW = 256;                      // weight leading dim (N total per seg)

    const int tid  = threadIdx.x;
    const int lane = tid & 31;
    const int warp = tid >> 5;
    const int wm   = warp >> 2;
    const int wn   = warp & 3;
    const int q    = lane >> 2;
    const int t4   = lane & 3;

    const int n0  = blockIdx.x * 128;
    const int m0  = blockIdx.y * 128;
    const int seg = n0 >> 8;
    const int ncol = n0 & 255;

    const float* W    = (seg == 0) ? Wa : (seg == 1) ? Wb : (seg == 2) ? Wc : Wd;
    const float* bias = (seg == 0) ? ba : (seg == 1) ? bb : (seg == 2) ? bc : bd;
    const float* Ap   = (MODE == 2) ? g_rp : (MODE == 4) ? g_x : A;

    float acc[4][4][4];
    #pragma unroll
    for (int i = 0; i < 4; i++)
        #pragma unroll
        for (int j = 0; j < 4; j++)
            #pragma unroll
            for (int v = 0; v < 4; v++) acc[i][j][v] = 0.f;

    auto load_chunk = [&](int bi, int k0) {
        #pragma unroll
        for (int i = 0; i < 4; i++) {
            int g = i * 256 + tid;
            int m = g >> 3, c4 = (g & 7) << 2;
            cp_async16(smem_u32(&As[bi][m * AS_STRIDE + c4]),
                       Ap + (size_t)(m0 + m) * LDA + k0 + c4);
        }
        #pragma unroll
        for (int i = 0; i < 4; i++) {
            int g = i * 256 + tid;
            int k = g >> 5, n4 = (g & 31) << 2;
            cp_async16(smem_u32(&Bs[bi][k * BS_STRIDE + n4]),
                       W + (size_t)(k0 + k) * LDW + ncol + n4);
        }
        cp_commit();
    };

    load_chunk(0, 0);

    for (int c = 0; c < KCH; c++) {
        const int buf = c & 1;
        if (c < KCH - 1) load_chunk(buf ^ 1, (c + 1) * 32);
        if (c < KCH - 1) cp_wait<1>(); else cp_wait<0>();
        __syncthreads();

        const float* Asb = As[buf];
        const float* Bsb = Bs[buf];
        #pragma unroll
        for (int kk = 0; kk < 4; kk++) {
            uint32_t a[4][4], b[4][2];
            const int col = kk * 8 + t4;
            #pragma unroll
            for (int mt = 0; mt < 4; mt++) {
                const int r0 = wm * 64 + mt * 16 + q;
                a[mt][0] = __float_as_uint(Asb[r0 * AS_STRIDE + col]);
                a[mt][1] = __float_as_uint(Asb[(r0 + 8) * AS_STRIDE + col]);
                a[mt][2] = __float_as_uint(Asb[r0 * AS_STRIDE + col + 4]);
                a[mt][3] = __float_as_uint(Asb[(r0 + 8) * AS_STRIDE + col + 4]);
            }
            #pragma unroll
            for (int nt = 0; nt < 4; nt++) {
                const int nb = wn * 32 + nt * 8 + q;
                b[nt][0] = __float_as_uint(Bsb[col * BS_STRIDE + nb]);
                b[nt][1] = __float_as_uint(Bsb[(col + 4) * BS_STRIDE + nb]);
            }
            #pragma unroll
            for (int mt = 0; mt < 4; mt++)
                #pragma unroll
                for (int nt = 0; nt < 4; nt++)
                    mma_tf32(acc[mt][nt], a[mt], b[nt]);
        }
        __syncthreads();
    }

    // ---------------- epilogue ----------------
    #pragma unroll
    for (int mt = 0; mt < 4; mt++) {
        #pragma unroll
        for (int nt = 0; nt < 4; nt++) {
            const int hl = wn * 32 + nt * 8 + 2 * t4;
            const int h  = ncol + hl;
            #pragma unroll
            for (int half = 0; half < 2; half++) {
                const int row = m0 + wm * 64 + mt * 16 + q + half * 8;
                const float v0 = acc[mt][nt][half * 2 + 0];
                const float v1 = acc[mt][nt][half * 2 + 1];
                if (MODE == 0) {
                    float2 bb2 = *(const float2*)(bias + h);
                    float2 o = make_float2(v0 + bb2.x, v1 + bb2.y);
                    *(float2*)(g_curx + (size_t)row * 1024 + seg * 256 + h) = o;
                } else if (MODE == 1) {
                    const int b = row / 10;
                    if (seg == 0) {
                        float2 cx = *(const float2*)(g_curx + (size_t)b * 1024 + h);
                        float2 o = make_float2(sigmoidf_(v0 + cx.x), sigmoidf_(v1 + cx.y));
                        *(float2*)(g_z + (size_t)row * 256 + h) = o;
                    } else {
                        float2 cx = *(const float2*)(g_curx + (size_t)b * 1024 + 256 + h);
                        float2 pv = *(const float2*)(prev + (size_t)row * 256 + h);
                        float2 o = make_float2(sigmoidf_(v0 + cx.x) * pv.x,
                                               sigmoidf_(v1 + cx.y) * pv.y);
                        *(float2*)(g_rp + (size_t)row * 256 + h) = o;
                    }
                } else if (MODE == 2) {
                    const int b = row / 10;
                    float2 cx = *(const float2*)(g_curx + (size_t)b * 1024 + 512 + h);
                    float2 zz = *(const float2*)(g_z + (size_t)row * 256 + h);
                    float2 pv = *(const float2*)(prev + (size_t)row * 256 + h);
                    float c0 = tanhf(v0 + cx.x), c1 = tanhf(v1 + cx.y);
                    float2 o = make_float2((1.f - zz.x) * pv.x + zz.x * c0,
                                           (1.f - zz.y) * pv.y + zz.y * c1);
                    *(float2*)(out + (size_t)row * 256 + h) = o;
                } else if (MODE == 3) {
                    float2 bb2 = *(const float2*)(bias + h);
                    float2 o = make_float2(v0 + bb2.x, v1 + bb2.y);
                    *(float2*)(g_k + (size_t)row * 256 + h) = o;
                } else {  // MODE 4: out projection -> g_f
                    float2 bb2 = *(const float2*)(bias + h);
                    float2 o = make_float2(v0 + bb2.x, v1 + bb2.y);
                    *(float2*)(g_f + (size_t)row * 256 + h) = o;
                }
            }
        }
    }
}

// ---------------------------------------------------------------------------
// attn_light: scores, softmax, head-mean, weighted memory. Writes x=[cur|wm]
// to g_x and attn weights to d_out. GB=32 batches/CTA. Memory-bound.
// ---------------------------------------------------------------------------
#define GB_ 32

__global__ __launch_bounds__(256)
void attn_light(const float* __restrict__ cur,
                float* __restrict__ d_out)
{
    __shared__ __align__(16) float sq[GB_ * 256];   // q
    __shared__ float ss[GB_ * 80];
    __shared__ float sattn[GB_ * 10];

    const int tid = threadIdx.x;
    const int b0 = blockIdx.x * GB_;
    const float* upd = d_out + (size_t)B_ * 256;
    float* attn_out  = d_out + (size_t)B_ * 256 + (size_t)BM_ * 256;

    // A: load q
    for (int idx = tid; idx < GB_ * 256; idx += 256) {
        int bi = idx >> 8, h = idx & 255;
        sq[bi * 256 + h] = g_curx[(size_t)(b0 + bi) * 1024 + 768 + h];
    }
    __syncthreads();

    // B: scores
    const float scale = 0.17677669529663687f;
    for (int t = tid; t < GB_ * 80; t += 256) {
        int bi = t / 80, rem = t % 80, n = rem / 10, m = rem % 10;
        const float* kp = g_k + ((size_t)((b0 + bi) * 10 + m)) * 256 + n * 32;
        const float* qp = sq + bi * 256 + n * 32;
        float s = 0.f;
        #pragma unroll
        for (int d4 = 0; d4 < 32; d4 += 4) {
            float4 kv = *(const float4*)(kp + d4);
            float4 qv = *(const float4*)(qp + d4);
            s += kv.x * qv.x + kv.y * qv.y + kv.z * qv.z + kv.w * qv.w;
        }
        ss[t] = s * scale;
    }
    __syncthreads();

    // C: softmax over m
    for (int t = tid; t < GB_ * 8; t += 256) {
        float* row = ss + t * 10;
        float mx = row[0];
        #pragma unroll
        for (int m = 1; m < 10; m++) mx = fmaxf(mx, row[m]);
        float e[10], sum = 0.f;
        #pragma unroll
        for (int m = 0; m < 10; m++) { e[m] = expf(row[m] - mx); sum += e[m]; }
        float inv = 1.f / sum;
        #pragma unroll
        for (int m = 0; m < 10; m++) row[m] = e[m] * inv;
    }
    __syncthreads();

    // head mean
    for (int t = tid; t < GB_ * 10; t += 256) {
        int bi = t / 10, m = t % 10;
        float s = 0.f;
        #pragma unroll
        for (int n = 0; n < 8; n++) s += ss[(bi * 8 + n) * 10 + m];
        s *= 0.125f;
        sattn[t] = s;
        attn_out[(size_t)(b0 + bi) * 10 + m] = s;
    }
    __syncthreads();

    // D: weighted memory; write x = [cur | weighted] to g_x
    for (int idx = tid; idx < GB_ * 256; idx += 256) {
        int bi = idx >> 8, h = idx & 255;
        size_t base = ((size_t)(b0 + bi) * 10) * 256 + h;
        float s = 0.f;
        #pragma unroll
        for (int m = 0; m < 10; m++) s += upd[base + m * 256] * sattn[bi * 10 + m];
        g_x[(size_t)(b0 + bi) * 512 + h]       = cur[(size_t)(b0 + bi) * 256 + h];
        g_x[(size_t)(b0 + bi) * 512 + 256 + h] = s;
    }
}

// ---------------------------------------------------------------------------
// LayerNorm over g_f -> d_out. One warp per row, 8 rows/CTA.
// ---------------------------------------------------------------------------
__global__ __launch_bounds__(256)
void ln_kernel(const float* __restrict__ gamma, const float* __restrict__ beta,
               float* __restrict__ d_out)
{
    const int warp = threadIdx.x >> 5;
    const int lane = threadIdx.x & 31;
    const int row  = blockIdx.x * 8 + warp;

    float v[8], sum = 0.f;
    const float* src = g_f + (size_t)row * 256;
    #pragma unroll
    for (int i = 0; i < 8; i++) { v[i] = src[lane + 32 * i]; sum += v[i]; }
    #pragma unroll
    for (int o = 16; o > 0; o >>= 1) sum += __shfl_xor_sync(0xffffffffu, sum, o);
    float mu = sum * (1.f / 256.f);
    float sq = 0.f;
    #pragma unroll
    for (int i = 0; i < 8; i++) { float d = v[i] - mu; sq += d * d; }
    #pragma unroll
    for (int o = 16; o > 0; o >>= 1) sq += __shfl_xor_sync(0xffffffffu, sq, o);
    float rstd = rsqrtf(sq * (1.f / 256.f) + 1e-5f);
    float* dst = d_out + (size_t)row * 256;
    #pragma unroll
    for (int i = 0; i < 8; i++) {
        int d_ = lane + 32 * i;
        dst[d_] = (v[i] - mu) * rstd * gamma[d_] + beta[d_];
    }
}

extern "C" void kernel_launch(void* const* d_in, const int* in_sizes, int n_in,
                              void* d_out, int out_size)
{
    (void)in_sizes; (void)n_in; (void)out_size;
    const float* cur    = (const float*)d_in[0];
    const float* prev   = (const float*)d_in[1];
    const float* Wz     = (const float*)d_in[2];
    const float* bz     = (const float*)d_in[3];
    const float* Wr     = (const float*)d_in[4];
    const float* br     = (const float*)d_in[5];
    const float* Wh     = (const float*)d_in[6];
    const float* bh     = (const float*)d_in[7];
    const float* Wq     = (const float*)d_in[8];
    const float* bq     = (const float*)d_in[9];
    const float* Wk     = (const float*)d_in[10];
    const float* bk     = (const float*)d_in[11];
    const float* Wo     = (const float*)d_in[12];
    const float* bo     = (const float*)d_in[13];
    const float* gamma2 = (const float*)d_in[14];
    const float* beta2  = (const float*)d_in[15];
    float* out = (float*)d_out;
    float* upd = out + (size_t)B_ * 256;

    dim3 blk(256);
    // 1) cur projections: [B,256] @ [256,1024]
    mma_gemm<0><<<dim3(8, B_ / 128), blk>>>(cur, Wz, Wr, Wh, Wq,
                                            bz, br, bh, bq, nullptr, nullptr);
    // 2) z/r gates: [BM,256] @ [256,512]
    mma_gemm<1><<<dim3(4, BM_ / 128), blk>>>(prev, Wz + 65536, Wr + 65536, nullptr, nullptr,
                                             nullptr, nullptr, nullptr, nullptr, prev, nullptr);
    // 3) cand + GRU update -> updated_memory
    mma_gemm<2><<<dim3(2, BM_ / 128), blk>>>(nullptr, Wh + 65536, nullptr, nullptr, nullptr,
                                             nullptr, nullptr, nullptr, nullptr, prev, upd);
    // 4) k projection
    mma_gemm<3><<<dim3(2, BM_ / 128), blk>>>(upd, Wk, nullptr, nullptr, nullptr,
                                             bk, nullptr, nullptr, nullptr, nullptr, nullptr);
    // 5) attention (scores/softmax/head-mean/weighted) -> g_x, attn weights
    attn_light<<<dim3(B_ / GB_), blk>>>(cur, out);
    // 6) output projection: [B,512] @ [512,256] -> g_f
    mma_gemm<4><<<dim3(2, B_ / 128), blk>>>(nullptr, Wo, nullptr, nullptr, nullptr,
                                            bo, nullptr, nullptr, nullptr, nullptr, nullptr);
    // 7) LayerNorm -> d_out
    ln_kernel<<<dim3(B_ / 8), blk>>>(gamma2, beta2, out);
}